// round 4
// baseline (speedup 1.0000x reference)
#include <cuda_runtime.h>
#include <cuda_bf16.h>

// Inputs (metadata order; NOTE int64 arrays are delivered as int32 by the harness):
//   d_in[0] vertex_attr : float32 [1000000, 2]
//   d_in[1] edgeij_pair : int32   [2, 16000000]   (row 0 = first 16M elems, contiguous)
//   d_in[2] edge_attr   : float32 [16000000, 2]
//   d_in[3] g           : float32 [1,1]          (unused)
//   d_in[4] batch       : int32   [1000000]      (unused)
// Output: float32 [1000000, 3] = concat(b_i, x_i, b_i - segsum(c_ij over edge src))

#define NV_MAX 1000000

__device__ float g_cbar[NV_MAX];

__global__ void zero_kernel(float4* __restrict__ cbar4, int n4) {
    int i = blockIdx.x * blockDim.x + threadIdx.x;
    if (i < n4) cbar4[i] = make_float4(0.f, 0.f, 0.f, 0.f);
}

// Each thread handles 4 edges: one int4 index load + two float4 attr loads.
__global__ void scatter_kernel(const int* __restrict__ idx,
                               const float* __restrict__ ea,
                               float* __restrict__ cbar,
                               int n_quads) {
    int t = blockIdx.x * blockDim.x + threadIdx.x;
    if (t >= n_quads) return;

    int4 i4 = reinterpret_cast<const int4*>(idx)[t];

    const float4* ep = reinterpret_cast<const float4*>(ea) + 2 * t;
    float4 e01 = ep[0];   // edges 4t, 4t+1 : (c0,c1, c0,c1)
    float4 e23 = ep[1];   // edges 4t+2, 4t+3

    atomicAdd(cbar + i4.x, e01.y);
    atomicAdd(cbar + i4.y, e01.w);
    atomicAdd(cbar + i4.z, e23.y);
    atomicAdd(cbar + i4.w, e23.w);
}

__global__ void finalize_kernel(const float2* __restrict__ va,
                                const float* __restrict__ cbar,
                                float* __restrict__ out,
                                int n) {
    int i = blockIdx.x * blockDim.x + threadIdx.x;
    if (i < n) {
        float2 v = va[i];
        float b = v.x;
        float x = v.y;
        float r = b - cbar[i];
        out[3 * i + 0] = b;
        out[3 * i + 1] = x;
        out[3 * i + 2] = r;
    }
}

extern "C" void kernel_launch(void* const* d_in, const int* in_sizes, int n_in,
                              void* d_out, int out_size) {
    const float2* vertex_attr = (const float2*)d_in[0];
    const int*    edge_src    = (const int*)d_in[1];     // row 0 of edgeij_pair (int32)
    const float*  edge_attr   = (const float*)d_in[2];
    float*        out         = (float*)d_out;

    const int n_vertices = in_sizes[0] / 2;
    const int n_edges    = in_sizes[2] / 2;
    const int n_quads    = n_edges / 4;     // 16M divisible by 4

    float* cbar;
    cudaGetSymbolAddress((void**)&cbar, g_cbar);

    {
        int n4 = n_vertices / 4;            // 1M divisible by 4
        int threads = 256;
        int blocks = (n4 + threads - 1) / threads;
        zero_kernel<<<blocks, threads>>>((float4*)cbar, n4);
    }
    {
        int threads = 256;
        int blocks = (n_quads + threads - 1) / threads;
        scatter_kernel<<<blocks, threads>>>(edge_src, edge_attr, cbar, n_quads);
    }
    {
        int threads = 256;
        int blocks = (n_vertices + threads - 1) / threads;
        finalize_kernel<<<blocks, threads>>>(vertex_attr, cbar, out, n_vertices);
    }
}